// round 1
// baseline (speedup 1.0000x reference)
#include <cuda_runtime.h>
#include <math.h>

#define T_  128
#define B_  32
#define I_  128
#define H_  128
#define R_  100
#define O_  64
#define RH_ (R_*H_)   // 12800

typedef unsigned long long u64;

// Scratch (static device globals: allowed; no runtime allocation)
static __device__ float g_inp[(size_t)T_*R_*B_*H_];   // [T][R][B][H]  input drive + bias
static __device__ float g_H  [(size_t)T_*B_*RH_];     // [T][B][R*H]   hidden history
static __device__ float g_msg[(size_t)R_*B_*H_];      // [R][B][H]     connectome message

// ---- packed f32x2 helpers (sm_103a) ----
__device__ __forceinline__ u64 pk2(float lo, float hi){
    u64 r; asm("mov.b64 %0, {%1,%2};" : "=l"(r) : "f"(lo), "f"(hi)); return r;
}
__device__ __forceinline__ void up2(u64 v, float& lo, float& hi){
    asm("mov.b64 {%0,%1}, %2;" : "=f"(lo), "=f"(hi) : "l"(v));
}
__device__ __forceinline__ u64 fma2(u64 a, u64 b, u64 c){
    u64 d; asm("fma.rn.f32x2 %0, %1, %2, %3;" : "=l"(d) : "l"(a), "l"(b), "l"(c)); return d;
}

// ============================================================================
// Kernel 1: inp[t,r,b,h] = sum_i x[t,b,i]*W_ih[r,i,h] + bias[r,h]
// grid (R, T), 256 threads. Thread owns (g, half of b). b packed in pairs.
// ============================================================================
__global__ __launch_bounds__(256) void inp_kernel(const float* __restrict__ x,
                                                  const float* __restrict__ W_ih,
                                                  const float* __restrict__ bias){
    int r = blockIdx.x, t = blockIdx.y;
    __shared__ u64 xs[16][128];                       // {x[2bb][k], x[2bb+1][k]}
    const float* xt = x + (size_t)t*B_*I_;
    for (int idx = threadIdx.x; idx < B_*I_; idx += 256){
        int b = idx >> 7, k = idx & 127;
        reinterpret_cast<float*>(&xs[b>>1][k])[b&1] = xt[idx];
    }
    __syncthreads();
    int g = threadIdx.x & 127, half = threadIdx.x >> 7;
    float bv = bias[r*H_ + g];
    u64 binit = pk2(bv, bv);
    u64 acc[8];
#pragma unroll
    for (int p=0;p<8;p++) acc[p] = binit;
    const float* W = W_ih + (size_t)r*I_*H_ + g;
#pragma unroll 4
    for (int k=0;k<I_;k++){
        float w = W[(size_t)k*H_];                    // coalesced over g
        u64 w2 = pk2(w, w);
#pragma unroll
        for (int p=0;p<8;p++) acc[p] = fma2(xs[half*8+p][k], w2, acc[p]);
    }
    float* op = g_inp + (size_t)(t*R_ + r)*B_*H_;
#pragma unroll
    for (int p=0;p<8;p++){
        int b0 = half*16 + 2*p;
        float lo, hi; up2(acc[p], lo, hi);
        op[b0*H_ + g]     = lo;
        op[(b0+1)*H_ + g] = hi;
    }
}

// ============================================================================
// Kernel 2: msg[j,b,h] = sum_i C[i,j]*H[t-1][i,b,h]
// grid (B, 10) : block owns one b and 10 j's; K=100 split in 2 smem chunks.
// ============================================================================
__global__ __launch_bounds__(128) void msg_kernel(const float* __restrict__ C, int t){
    int b = blockIdx.x;
    int jbase = blockIdx.y * 10;
    __shared__ float Hs[50][128];
    __shared__ u64 Cs[100][5];                        // {C[i][j0+2jj], C[i][j0+2jj+1]}
    for (int idx = threadIdx.x; idx < 500; idx += 128){
        int i = idx/5, jj = idx%5;
        Cs[i][jj] = pk2(C[i*R_ + jbase + 2*jj], C[i*R_ + jbase + 2*jj + 1]);
    }
    u64 acc[5] = {0,0,0,0,0};
    const float* Hp = g_H + ((size_t)(t-1)*B_ + b)*RH_;   // contiguous [R*H]
    int h = threadIdx.x;
    for (int chunk=0; chunk<2; chunk++){
        __syncthreads();
        for (int idx = threadIdx.x; idx < 50*128; idx += 128)
            Hs[idx>>7][idx&127] = Hp[chunk*50*128 + idx];
        __syncthreads();
#pragma unroll 2
        for (int ii=0; ii<50; ii++){
            float hv = Hs[ii][h];
            u64 hv2 = pk2(hv, hv);
            int i = chunk*50 + ii;
#pragma unroll
            for (int jj=0;jj<5;jj++) acc[jj] = fma2(Cs[i][jj], hv2, acc[jj]);
        }
    }
#pragma unroll
    for (int jj=0;jj<5;jj++){
        float lo, hi; up2(acc[jj], lo, hi);
        g_msg[(size_t)(jbase+2*jj  )*B_*H_ + b*H_ + h] = lo;
        g_msg[(size_t)(jbase+2*jj+1)*B_*H_ + b*H_ + h] = hi;
    }
}

// ============================================================================
// Kernel 3: H[t][b][r*H+g] = tanh(inp + Hprev[r]@W_hh[r] + msg[r]@W_rhh[r])
// grid (R), 512 threads. Thread owns (g, 4 b-pairs). smem operands pre-paired
// so all main-loop LDS are warp-broadcast.
// ============================================================================
__global__ __launch_bounds__(512) void step_kernel(const float* __restrict__ W_hh,
                                                   const float* __restrict__ W_rhh,
                                                   int t){
    int r = blockIdx.x;
    __shared__ u64 hs[16][128];
    __shared__ u64 ms[16][128];
    int tid = threadIdx.x;
    int g = tid & 127, bq = tid >> 7;                 // bq 0..3 -> b in [bq*8, bq*8+8)
    u64 acc[4];
    const float* ip = g_inp + (size_t)(t*R_ + r)*B_*H_;
#pragma unroll
    for (int p=0;p<4;p++){
        int b0 = bq*8 + 2*p;
        acc[p] = pk2(ip[b0*H_ + g], ip[(b0+1)*H_ + g]);
    }
    if (t > 0){
        const float* Hp = g_H + (size_t)(t-1)*B_*RH_;
        const float* Mp = g_msg + (size_t)r*B_*H_;
        for (int idx = tid; idx < B_*H_; idx += 512){
            int b = idx >> 7, k = idx & 127;
            reinterpret_cast<float*>(&hs[b>>1][k])[b&1] = Hp[(size_t)b*RH_ + r*H_ + k];
            reinterpret_cast<float*>(&ms[b>>1][k])[b&1] = Mp[idx];
        }
        __syncthreads();
        const float* Wl = W_hh  + (size_t)r*H_*H_ + g;
        const float* Wc = W_rhh + (size_t)r*H_*H_ + g;
#pragma unroll 2
        for (int k=0;k<H_;k++){
            float w1 = Wl[(size_t)k*H_];              // coalesced over g, L2-resident
            float w2 = Wc[(size_t)k*H_];
            u64 w1d = pk2(w1, w1), w2d = pk2(w2, w2);
#pragma unroll
            for (int p=0;p<4;p++){
                acc[p] = fma2(hs[bq*4+p][k], w1d, acc[p]);
                acc[p] = fma2(ms[bq*4+p][k], w2d, acc[p]);
            }
        }
    }
    float* Ho = g_H + (size_t)t*B_*RH_;
#pragma unroll
    for (int p=0;p<4;p++){
        int b0 = bq*8 + 2*p;
        float lo, hi; up2(acc[p], lo, hi);
        Ho[(size_t)b0*RH_     + r*H_ + g] = tanhf(lo);
        Ho[(size_t)(b0+1)*RH_ + r*H_ + g] = tanhf(hi);
    }
}

// ============================================================================
// Kernel 4: out[t,b,o] = H[t][b][:] @ W_out + b_out
// grid (T), 128 threads. Thread owns 2 rows x 8 o's; W loaded as 128-bit
// vectors (o-pairs are native f32x2 operands, no packing movs).
// ============================================================================
__global__ __launch_bounds__(128) void out_kernel(const float* __restrict__ W_out,
                                                  const float* __restrict__ b_out,
                                                  float* __restrict__ out){
    int t = blockIdx.x;
    __shared__ float hsh[32][128];
    int tid = threadIdx.x;
    int og = tid & 7, rg = tid >> 3;                  // og 0..7 -> o0 = og*8 ; rg 0..15 -> rows rg*2,rg*2+1
    int o0 = og*8, b0 = rg*2;
    u64 acc[2][4];
    {
        const ulonglong2* bo = reinterpret_cast<const ulonglong2*>(b_out + o0);
        ulonglong2 q0 = bo[0], q1 = bo[1];
#pragma unroll
        for (int p=0;p<2;p++){ acc[p][0]=q0.x; acc[p][1]=q0.y; acc[p][2]=q1.x; acc[p][3]=q1.y; }
    }
    const float* Hb = g_H + (size_t)t*B_*RH_;
    for (int kt=0; kt<RH_/128; kt++){
        __syncthreads();
        for (int idx = tid; idx < 32*128; idx += 128){
            int b = idx >> 7, kk = idx & 127;
            hsh[b][kk] = Hb[(size_t)b*RH_ + kt*128 + kk];
        }
        __syncthreads();
#pragma unroll 4
        for (int kk=0; kk<128; kk++){
            int k = kt*128 + kk;
            const ulonglong2* wp = reinterpret_cast<const ulonglong2*>(W_out + (size_t)k*O_ + o0);
            ulonglong2 w0 = wp[0], w1 = wp[1];
            float h0 = hsh[b0][kk], h1 = hsh[b0+1][kk];
            u64 h0d = pk2(h0, h0), h1d = pk2(h1, h1);
            acc[0][0] = fma2(w0.x, h0d, acc[0][0]);
            acc[0][1] = fma2(w0.y, h0d, acc[0][1]);
            acc[0][2] = fma2(w1.x, h0d, acc[0][2]);
            acc[0][3] = fma2(w1.y, h0d, acc[0][3]);
            acc[1][0] = fma2(w0.x, h1d, acc[1][0]);
            acc[1][1] = fma2(w0.y, h1d, acc[1][1]);
            acc[1][2] = fma2(w1.x, h1d, acc[1][2]);
            acc[1][3] = fma2(w1.y, h1d, acc[1][3]);
        }
    }
    u64* op = reinterpret_cast<u64*>(out);
#pragma unroll
    for (int p=0;p<2;p++){
        size_t base = ((size_t)(t*B_ + b0 + p)*O_ + o0) >> 1;
#pragma unroll
        for (int j=0;j<4;j++) op[base + j] = acc[p][j];
    }
}

// ============================================================================
// Launch: inp precompute, 128 recurrent steps (msg + step), final projection.
// Inputs (metadata order): x, C, W_ih, W_hh, W_rhh, bias, W_out, b_out
// ============================================================================
extern "C" void kernel_launch(void* const* d_in, const int* in_sizes, int n_in,
                              void* d_out, int out_size){
    const float* x     = (const float*)d_in[0];
    const float* C     = (const float*)d_in[1];
    const float* W_ih  = (const float*)d_in[2];
    const float* W_hh  = (const float*)d_in[3];
    const float* W_rhh = (const float*)d_in[4];
    const float* bias  = (const float*)d_in[5];
    const float* W_out = (const float*)d_in[6];
    const float* b_out = (const float*)d_in[7];
    float* out = (float*)d_out;

    inp_kernel<<<dim3(R_, T_), 256>>>(x, W_ih, bias);

    for (int t = 0; t < T_; t++){
        if (t > 0)
            msg_kernel<<<dim3(B_, R_/10), 128>>>(C, t);
        step_kernel<<<R_, 512>>>(W_hh, W_rhh, t);
    }

    out_kernel<<<T_, 128>>>(W_out, b_out, out);
}

// round 2
// speedup vs baseline: 1.2270x; 1.2270x over previous
#include <cuda_runtime.h>
#include <math.h>

#define T_  128
#define B_  32
#define I_  128
#define H_  128
#define R_  100
#define O_  64
#define RH_ (R_*H_)   // 12800

typedef unsigned long long u64;

// Scratch (static device globals)
static __device__ float g_inp[(size_t)T_*R_*B_*H_];   // [T][R][B][H]
static __device__ float g_H  [(size_t)T_*B_*RH_];     // [T][B][R*H]
static __device__ float g_msg[(size_t)R_*B_*H_];      // [R][B][H]
static __device__ unsigned g_arrive;                  // grid-barrier counter

// ---- packed f32x2 helpers (sm_103a) ----
__device__ __forceinline__ u64 pk2(float lo, float hi){
    u64 r; asm("mov.b64 %0, {%1,%2};" : "=l"(r) : "f"(lo), "f"(hi)); return r;
}
__device__ __forceinline__ void up2(u64 v, float& lo, float& hi){
    asm("mov.b64 {%0,%1}, %2;" : "=f"(lo), "=f"(hi) : "l"(v));
}
__device__ __forceinline__ u64 fma2(u64 a, u64 b, u64 c){
    u64 d; asm("fma.rn.f32x2 %0, %1, %2, %3;" : "=l"(d) : "l"(a), "l"(b), "l"(c)); return d;
}

// ============================================================================
// Kernel 1: inp[t,r,b,h] = sum_i x[t,b,i]*W_ih[r,i,h] + bias[r,h]
// Also resets the grid-barrier counter (runs before the persistent kernel).
// ============================================================================
__global__ __launch_bounds__(256) void inp_kernel(const float* __restrict__ x,
                                                  const float* __restrict__ W_ih,
                                                  const float* __restrict__ bias){
    if (blockIdx.x == 0 && blockIdx.y == 0 && threadIdx.x == 0) g_arrive = 0u;

    int r = blockIdx.x, t = blockIdx.y;
    __shared__ u64 xs[16][128];                       // {x[2bb][k], x[2bb+1][k]}
    const float* xt = x + (size_t)t*B_*I_;
    for (int idx = threadIdx.x; idx < B_*I_; idx += 256){
        int b = idx >> 7, k = idx & 127;
        reinterpret_cast<float*>(&xs[b>>1][k])[b&1] = xt[idx];
    }
    __syncthreads();
    int g = threadIdx.x & 127, half = threadIdx.x >> 7;
    float bv = bias[r*H_ + g];
    u64 binit = pk2(bv, bv);
    u64 acc[8];
#pragma unroll
    for (int p=0;p<8;p++) acc[p] = binit;
    const float* W = W_ih + (size_t)r*I_*H_ + g;
#pragma unroll 4
    for (int k=0;k<I_;k++){
        float w = W[(size_t)k*H_];
        u64 w2 = pk2(w, w);
#pragma unroll
        for (int p=0;p<8;p++) acc[p] = fma2(xs[half*8+p][k], w2, acc[p]);
    }
    float* op = g_inp + (size_t)(t*R_ + r)*B_*H_;
#pragma unroll
    for (int p=0;p<8;p++){
        int b0 = half*16 + 2*p;
        float lo, hi; up2(acc[p], lo, hi);
        op[b0*H_ + g]     = lo;
        op[(b0+1)*H_ + g] = hi;
    }
}

// ============================================================================
// Persistent recurrent kernel: grid = 100 blocks (one per region), 256 thr.
// smem: W_hh[r] (64KB) + W_rhh[r] (64KB) + C (40KB) + hT/mT staging (36KB).
// Per step: phase A (msg, blocks 0..63) -> grid bar -> phase B -> grid bar.
// ============================================================================
#define SM_W1   0
#define SM_W2   16384
#define SM_C    32768
#define SM_HT   43008          // 128 rows x 36 floats (pad for banks)
#define SM_MT   47616
#define SM_FLOATS 52224        // 208896 bytes

__device__ __forceinline__ void gbar(unsigned target){
    __syncthreads();
    if (threadIdx.x == 0){
        __threadfence();
        atomicAdd(&g_arrive, 1u);
        volatile unsigned* va = &g_arrive;
        while (*va < target) __nanosleep(64);
        __threadfence();
    }
    __syncthreads();
}

// msg inner body: CNT j-pairs at columns c0, c0+1
template<int CNT>
__device__ __forceinline__ void msg_body(const float* __restrict__ Cs,
                                         const float* __restrict__ Hs,
                                         int c0, int jp0, int b, int hh){
    u64 acc[CNT*2];
#pragma unroll
    for (int j=0;j<CNT*2;j++) acc[j] = 0ull;
    for (int i=0;i<R_;i++){
        float2 hp = *reinterpret_cast<const float2*>(Hs + i*64 + c0);
        u64 h0 = pk2(hp.x, hp.x), h1 = pk2(hp.y, hp.y);
        const float* Cr = Cs + i*R_ + jp0*2;
#pragma unroll
        for (int j=0;j<CNT;j++){
            u64 cv = *reinterpret_cast<const u64*>(Cr + 2*j);  // LDS.64 broadcast
            acc[j*2+0] = fma2(cv, h0, acc[j*2+0]);
            acc[j*2+1] = fma2(cv, h1, acc[j*2+1]);
        }
    }
#pragma unroll
    for (int j=0;j<CNT;j++){
#pragma unroll
        for (int cc=0;cc<2;cc++){
            float lo, hi; up2(acc[j*2+cc], lo, hi);
            int jA = jp0*2 + 2*j, jB = jA + 1;
            int col = hh*64 + c0 + cc;
            g_msg[(size_t)jA*B_*H_ + b*H_ + col] = lo;
            g_msg[(size_t)jB*B_*H_ + b*H_ + col] = hi;
        }
    }
}

__global__ __launch_bounds__(256,1) void rnn_persist(const float* __restrict__ W_hh,
                                                     const float* __restrict__ W_rhh,
                                                     const float* __restrict__ C){
    extern __shared__ float sm[];
    float* w1 = sm + SM_W1;
    float* w2 = sm + SM_W2;
    float* Cs = sm + SM_C;
    float* hT = sm + SM_HT;
    float* mT = sm + SM_MT;
    float* Hs = hT;                 // overlay (msg phase uses 6400 floats here)

    const int r = blockIdx.x, tid = threadIdx.x;

    // ---- one-time staging: region weights + connectome ----
    {
        const float4* a = reinterpret_cast<const float4*>(W_hh  + (size_t)r*H_*H_);
        const float4* b = reinterpret_cast<const float4*>(W_rhh + (size_t)r*H_*H_);
        float4* d1 = reinterpret_cast<float4*>(w1);
        float4* d2 = reinterpret_cast<float4*>(w2);
        for (int i=tid;i<4096;i+=256){ d1[i]=a[i]; d2[i]=b[i]; }
        const float4* c4 = reinterpret_cast<const float4*>(C);
        float4* dc = reinterpret_cast<float4*>(Cs);
        for (int i=tid;i<2500;i+=256) dc[i]=c4[i];
    }

    const int l  = tid & 31, w = tid >> 5;
    const int bg = w & 3, gh = w >> 2;
    const int g0 = gh*64 + l;                 // columns g0 and g0+32
    const int b0 = bg*8;

    unsigned bars = 0;

    for (int t = 0; t < T_; t++){
        // ---------------- phase A: msg (t>0, blocks 0..63) ----------------
        if (t > 0){
            if (r < 64){
                int b  = r >> 1, hh = r & 1;
                const float* Hp = g_H + ((size_t)(t-1)*B_ + b)*RH_ + hh*64;
                for (int idx=tid; idx<6400; idx+=256){
                    int i = idx >> 6, c = idx & 63;
                    Hs[idx] = Hp[(size_t)i*H_ + c];
                }
                __syncthreads();
                int cg = tid & 31, c0 = cg*2;
                int jg = tid >> 5;
                if (jg < 2) msg_body<7>(Cs, Hs, c0, jg*7,            b, hh);
                else        msg_body<6>(Cs, Hs, c0, 14 + (jg-2)*6,   b, hh);
            }
            gbar(++bars * (unsigned)R_);
        }

        // ---------------- phase B: H[t] = tanh(inp + loc + cross) ----------
        u64 acc[8];                         // [p][e]: 4 b-pairs x 2 g-cols
        {
            const float* ip = g_inp + ((size_t)t*R_ + r)*B_*H_;
#pragma unroll
            for (int p=0;p<4;p++){
#pragma unroll
                for (int e=0;e<2;e++){
                    int g = g0 + e*32;
                    acc[p*2+e] = pk2(ip[(b0+2*p)*H_ + g], ip[(b0+2*p+1)*H_ + g]);
                }
            }
        }
        if (t > 0){
            // stage H[t-1] region-slice and msg[r] transposed into smem
            const float* Hp = g_H  + (size_t)(t-1)*B_*RH_ + (size_t)r*H_;
            const float* Mp = g_msg + (size_t)r*B_*H_;
            for (int idx=tid; idx<4096; idx+=256){
                int b = idx >> 7, k = idx & 127;
                hT[k*36 + b] = Hp[(size_t)b*RH_ + k];
                mT[k*36 + b] = Mp[idx];
            }
            __syncthreads();
#pragma unroll 8
            for (int k=0;k<H_;k++){
                float w1a = w1[k*H_ + g0], w1b = w1[k*H_ + g0 + 32];
                float w2a = w2[k*H_ + g0], w2b = w2[k*H_ + g0 + 32];
                u64 w1ad = pk2(w1a,w1a), w1bd = pk2(w1b,w1b);
                u64 w2ad = pk2(w2a,w2a), w2bd = pk2(w2b,w2b);
                ulonglong2 hA = *reinterpret_cast<const ulonglong2*>(hT + k*36 + b0);
                ulonglong2 hB = *reinterpret_cast<const ulonglong2*>(hT + k*36 + b0 + 4);
                ulonglong2 mA = *reinterpret_cast<const ulonglong2*>(mT + k*36 + b0);
                ulonglong2 mB = *reinterpret_cast<const ulonglong2*>(mT + k*36 + b0 + 4);
                acc[0] = fma2(hA.x, w1ad, acc[0]);  acc[0] = fma2(mA.x, w2ad, acc[0]);
                acc[1] = fma2(hA.x, w1bd, acc[1]);  acc[1] = fma2(mA.x, w2bd, acc[1]);
                acc[2] = fma2(hA.y, w1ad, acc[2]);  acc[2] = fma2(mA.y, w2ad, acc[2]);
                acc[3] = fma2(hA.y, w1bd, acc[3]);  acc[3] = fma2(mA.y, w2bd, acc[3]);
                acc[4] = fma2(hB.x, w1ad, acc[4]);  acc[4] = fma2(mB.x, w2ad, acc[4]);
                acc[5] = fma2(hB.x, w1bd, acc[5]);  acc[5] = fma2(mB.x, w2bd, acc[5]);
                acc[6] = fma2(hB.y, w1ad, acc[6]);  acc[6] = fma2(mB.y, w2ad, acc[6]);
                acc[7] = fma2(hB.y, w1bd, acc[7]);  acc[7] = fma2(mB.y, w2bd, acc[7]);
            }
        }
        {
            float* Ho = g_H + (size_t)t*B_*RH_ + (size_t)r*H_;
#pragma unroll
            for (int p=0;p<4;p++){
#pragma unroll
                for (int e=0;e<2;e++){
                    float lo, hi; up2(acc[p*2+e], lo, hi);
                    int g = g0 + e*32;
                    Ho[(size_t)(b0+2*p)*RH_   + g] = tanhf(lo);
                    Ho[(size_t)(b0+2*p+1)*RH_ + g] = tanhf(hi);
                }
            }
        }
        if (t < T_-1) gbar(++bars * (unsigned)R_);
    }
}

// ============================================================================
// Kernel 3: out[t,b,o] = H[t][b][:] @ W_out + b_out
// ============================================================================
__global__ __launch_bounds__(128) void out_kernel(const float* __restrict__ W_out,
                                                  const float* __restrict__ b_out,
                                                  float* __restrict__ out){
    int t = blockIdx.x;
    __shared__ float hsh[32][128];
    int tid = threadIdx.x;
    int og = tid & 7, rg = tid >> 3;
    int o0 = og*8, b0 = rg*2;
    u64 acc[2][4];
    {
        const ulonglong2* bo = reinterpret_cast<const ulonglong2*>(b_out + o0);
        ulonglong2 q0 = bo[0], q1 = bo[1];
#pragma unroll
        for (int p=0;p<2;p++){ acc[p][0]=q0.x; acc[p][1]=q0.y; acc[p][2]=q1.x; acc[p][3]=q1.y; }
    }
    const float* Hb = g_H + (size_t)t*B_*RH_;
    for (int kt=0; kt<RH_/128; kt++){
        __syncthreads();
        for (int idx = tid; idx < 32*128; idx += 128){
            int b = idx >> 7, kk = idx & 127;
            hsh[b][kk] = Hb[(size_t)b*RH_ + kt*128 + kk];
        }
        __syncthreads();
#pragma unroll 4
        for (int kk=0; kk<128; kk++){
            int k = kt*128 + kk;
            const ulonglong2* wp = reinterpret_cast<const ulonglong2*>(W_out + (size_t)k*O_ + o0);
            ulonglong2 w0 = wp[0], w1 = wp[1];
            float h0 = hsh[b0][kk], h1 = hsh[b0+1][kk];
            u64 h0d = pk2(h0, h0), h1d = pk2(h1, h1);
            acc[0][0] = fma2(w0.x, h0d, acc[0][0]);
            acc[0][1] = fma2(w0.y, h0d, acc[0][1]);
            acc[0][2] = fma2(w1.x, h0d, acc[0][2]);
            acc[0][3] = fma2(w1.y, h0d, acc[0][3]);
            acc[1][0] = fma2(w0.x, h1d, acc[1][0]);
            acc[1][1] = fma2(w0.y, h1d, acc[1][1]);
            acc[1][2] = fma2(w1.x, h1d, acc[1][2]);
            acc[1][3] = fma2(w1.y, h1d, acc[1][3]);
        }
    }
    u64* op = reinterpret_cast<u64*>(out);
#pragma unroll
    for (int p=0;p<2;p++){
        size_t base = ((size_t)(t*B_ + b0 + p)*O_ + o0) >> 1;
#pragma unroll
        for (int j=0;j<4;j++) op[base + j] = acc[p][j];
    }
}

// ============================================================================
// Launch
// ============================================================================
extern "C" void kernel_launch(void* const* d_in, const int* in_sizes, int n_in,
                              void* d_out, int out_size){
    const float* x     = (const float*)d_in[0];
    const float* C     = (const float*)d_in[1];
    const float* W_ih  = (const float*)d_in[2];
    const float* W_hh  = (const float*)d_in[3];
    const float* W_rhh = (const float*)d_in[4];
    const float* bias  = (const float*)d_in[5];
    const float* W_out = (const float*)d_in[6];
    const float* b_out = (const float*)d_in[7];
    float* out = (float*)d_out;

    cudaFuncSetAttribute(rnn_persist, cudaFuncAttributeMaxDynamicSharedMemorySize,
                         SM_FLOATS * (int)sizeof(float));

    inp_kernel<<<dim3(R_, T_), 256>>>(x, W_ih, bias);     // also resets g_arrive
    rnn_persist<<<R_, 256, SM_FLOATS * sizeof(float)>>>(W_hh, W_rhh, C);
    out_kernel<<<T_, 128>>>(W_out, b_out, out);
}

// round 3
// speedup vs baseline: 1.5791x; 1.2870x over previous
#include <cuda_runtime.h>
#include <math.h>

#define T_  128
#define B_  32
#define I_  128
#define H_  128
#define R_  100
#define O_  64
#define RH_ (R_*H_)   // 12800

typedef unsigned long long u64;

// Scratch (static device globals)
static __device__ float g_inp[(size_t)T_*R_*B_*H_];   // [T][R][B][H]
static __device__ float g_H  [(size_t)T_*B_*RH_];     // [T][B][R*H]
static __device__ float g_msg[(size_t)R_*B_*H_];      // [R][B][H]
static __device__ unsigned g_arrive;                  // grid-barrier counter

// ---- packed f32x2 helpers (sm_103a) ----
__device__ __forceinline__ u64 pk2(float lo, float hi){
    u64 r; asm("mov.b64 %0, {%1,%2};" : "=l"(r) : "f"(lo), "f"(hi)); return r;
}
__device__ __forceinline__ void up2(u64 v, float& lo, float& hi){
    asm("mov.b64 {%0,%1}, %2;" : "=f"(lo), "=f"(hi) : "l"(v));
}
__device__ __forceinline__ u64 fma2(u64 a, u64 b, u64 c){
    u64 d; asm("fma.rn.f32x2 %0, %1, %2, %3;" : "=l"(d) : "l"(a), "l"(b), "l"(c)); return d;
}

// ============================================================================
// Kernel 1: inp[t,r,b,h] = sum_i x[t,b,i]*W_ih[r,i,h] + bias[r,h]
// 256 thr: thread owns 2 g-cols {gg, gg+64} x 4 b-pairs -> fma2:LDS = 2:1.
// Also resets the grid-barrier counter.
// ============================================================================
__global__ __launch_bounds__(256) void inp_kernel(const float* __restrict__ x,
                                                  const float* __restrict__ W_ih,
                                                  const float* __restrict__ bias){
    if (blockIdx.x == 0 && blockIdx.y == 0 && threadIdx.x == 0) g_arrive = 0u;

    int r = blockIdx.x, t = blockIdx.y;
    __shared__ u64 xs[16][128];                       // {x[2bb][k], x[2bb+1][k]}
    const float* xt = x + (size_t)t*B_*I_;
    for (int idx = threadIdx.x; idx < B_*I_; idx += 256){
        int b = idx >> 7, k = idx & 127;
        reinterpret_cast<float*>(&xs[b>>1][k])[b&1] = xt[idx];
    }
    __syncthreads();

    int gg = threadIdx.x & 63, quad = threadIdx.x >> 6;   // quad: 4 b-quads of 8 b
    float bva = bias[r*H_ + gg], bvb = bias[r*H_ + gg + 64];
    u64 acc[8];                                           // [pair p 0..3][col e 0..1]
#pragma unroll
    for (int p=0;p<4;p++){ acc[p*2+0] = pk2(bva,bva); acc[p*2+1] = pk2(bvb,bvb); }

    const float* W = W_ih + (size_t)r*I_*H_;
#pragma unroll 4
    for (int k=0;k<I_;k++){
        float wa = W[(size_t)k*H_ + gg];
        float wb = W[(size_t)k*H_ + gg + 64];
        u64 wad = pk2(wa,wa), wbd = pk2(wb,wb);
#pragma unroll
        for (int p=0;p<4;p++){
            u64 xv = xs[quad*4+p][k];                     // broadcast LDS.64
            acc[p*2+0] = fma2(xv, wad, acc[p*2+0]);
            acc[p*2+1] = fma2(xv, wbd, acc[p*2+1]);
        }
    }
    float* op = g_inp + (size_t)(t*R_ + r)*B_*H_;
#pragma unroll
    for (int p=0;p<4;p++){
        int b0 = quad*8 + 2*p;
#pragma unroll
        for (int e=0;e<2;e++){
            float lo, hi; up2(acc[p*2+e], lo, hi);
            op[b0*H_     + gg + e*64] = lo;
            op[(b0+1)*H_ + gg + e*64] = hi;
        }
    }
}

// ============================================================================
// Persistent recurrent kernel: grid = 100 blocks, 512 threads.
// smem: W_hh[r] | W_rhh[r] | C | hT | mT   (Hs for msg overlays hT/mT)
// ============================================================================
#define SM_W1   0
#define SM_W2   16384
#define SM_C    32768
#define SM_HT   42768          // 128 rows x 36 floats
#define SM_MT   47376
#define SM_FLOATS 51984        // 207936 bytes

__device__ __forceinline__ void gbar(unsigned target){
    __threadfence();
    __syncthreads();
    if (threadIdx.x == 0){
        atomicAdd(&g_arrive, 1u);
        volatile unsigned* va = &g_arrive;
        while (*va < target) { }
    }
    __syncthreads();
}

// msg inner body: NP j-pairs, 2 h-columns (c0, c0+1)
template<int NP>
__device__ __forceinline__ void msg_body(const float* __restrict__ Cs,
                                         const float* __restrict__ Hs,
                                         int c0, int jp0, int b, int hh){
    u64 acc[NP*2];
#pragma unroll
    for (int j=0;j<NP*2;j++) acc[j] = 0ull;
#pragma unroll 2
    for (int i=0;i<R_;i++){
        float2 hp = *reinterpret_cast<const float2*>(Hs + i*64 + c0);
        u64 h0 = pk2(hp.x, hp.x), h1 = pk2(hp.y, hp.y);
        const float* Cr = Cs + i*R_ + jp0*2;
#pragma unroll
        for (int j=0;j<NP;j++){
            u64 cv = *reinterpret_cast<const u64*>(Cr + 2*j);  // broadcast LDS.64
            acc[j*2+0] = fma2(cv, h0, acc[j*2+0]);
            acc[j*2+1] = fma2(cv, h1, acc[j*2+1]);
        }
    }
#pragma unroll
    for (int j=0;j<NP;j++){
        int jA = jp0*2 + 2*j, jB = jA + 1;
#pragma unroll
        for (int cc=0;cc<2;cc++){
            float lo, hi; up2(acc[j*2+cc], lo, hi);
            int col = hh*64 + c0 + cc;
            __stcg(&g_msg[(size_t)jA*B_*H_ + b*H_ + col], lo);
            __stcg(&g_msg[(size_t)jB*B_*H_ + b*H_ + col], hi);
        }
    }
}

__global__ __launch_bounds__(512,1) void rnn_persist(const float* __restrict__ W_hh,
                                                     const float* __restrict__ W_rhh,
                                                     const float* __restrict__ C){
    extern __shared__ float sm[];
    float* w1 = sm + SM_W1;
    float* w2 = sm + SM_W2;
    float* Cs = sm + SM_C;
    float* hT = sm + SM_HT;
    float* mT = sm + SM_MT;
    float* Hs = hT;                       // overlay for msg phase (6400 floats)

    const int r = blockIdx.x, tid = threadIdx.x;

    // one-time staging: region weights + connectome
    {
        const float4* a  = reinterpret_cast<const float4*>(W_hh  + (size_t)r*H_*H_);
        const float4* bb = reinterpret_cast<const float4*>(W_rhh + (size_t)r*H_*H_);
        float4* d1 = reinterpret_cast<float4*>(w1);
        float4* d2 = reinterpret_cast<float4*>(w2);
        for (int i=tid;i<4096;i+=512){ d1[i]=a[i]; d2[i]=bb[i]; }
        const float4* c4 = reinterpret_cast<const float4*>(C);
        float4* dc = reinterpret_cast<float4*>(Cs);
        for (int i=tid;i<2500;i+=512) dc[i]=c4[i];
    }

    // phase-B mapping: 2 g-cols x 2 b-pairs per thread
    const int gg = tid & 63;
    const int bq = tid >> 6;              // 0..7
    const int b0 = bq*4;                  // 4 b's = 2 pairs
    // phase-A mapping: 2 h-cols x (3..4) j-pairs
    const int cg = tid & 31, c0 = cg*2;
    const int jg = tid >> 5;              // 0..15
    const int jp0 = (jg<2)? jg*4 : 8 + (jg-2)*3;

    unsigned bars = 0;

    for (int t = 0; t < T_; t++){
        // ------------- phase A: msg (blocks 0..63) -------------
        if (t > 0){
            if (r < 64){
                int b  = r >> 1, hh = r & 1;
                const float* Hp = g_H + ((size_t)(t-1)*B_ + b)*RH_ + hh*64;
                for (int idx=tid; idx<6400; idx+=512)
                    Hs[idx] = __ldcg(Hp + (size_t)(idx>>6)*H_ + (idx&63));
                __syncthreads();
                if (jg < 2) msg_body<4>(Cs, Hs, c0, jp0, b, hh);
                else        msg_body<3>(Cs, Hs, c0, jp0, b, hh);
            }
            gbar(++bars * (unsigned)R_);
        }

        // ------------- phase B: H[t] = tanh(inp + loc + cross) -------------
        u64 acc[4];
        {
            const float* ip = g_inp + ((size_t)t*R_ + r)*B_*H_;
#pragma unroll
            for (int p=0;p<2;p++){
#pragma unroll
                for (int e=0;e<2;e++){
                    int g = gg + e*64;
                    acc[p*2+e] = pk2(ip[(b0+2*p)*H_ + g], ip[(b0+2*p+1)*H_ + g]);
                }
            }
        }
        if (t > 0){
            const float* Hp = g_H  + (size_t)(t-1)*B_*RH_ + (size_t)r*H_;
            const float* Mp = g_msg + (size_t)r*B_*H_;
            for (int idx=tid; idx<4096; idx+=512){
                int b = idx >> 7, k = idx & 127;
                hT[k*36 + b] = __ldcg(Hp + (size_t)b*RH_ + k);
                mT[k*36 + b] = __ldcg(Mp + idx);
            }
            __syncthreads();
#pragma unroll 4
            for (int k=0;k<H_;k++){
                float w1a = w1[k*H_ + gg], w1b = w1[k*H_ + gg + 64];
                float w2a = w2[k*H_ + gg], w2b = w2[k*H_ + gg + 64];
                u64 w1ad = pk2(w1a,w1a), w1bd = pk2(w1b,w1b);
                u64 w2ad = pk2(w2a,w2a), w2bd = pk2(w2b,w2b);
                ulonglong2 hA = *reinterpret_cast<const ulonglong2*>(hT + k*36 + b0);
                ulonglong2 mA = *reinterpret_cast<const ulonglong2*>(mT + k*36 + b0);
                acc[0] = fma2(hA.x, w1ad, acc[0]);  acc[0] = fma2(mA.x, w2ad, acc[0]);
                acc[1] = fma2(hA.x, w1bd, acc[1]);  acc[1] = fma2(mA.x, w2bd, acc[1]);
                acc[2] = fma2(hA.y, w1ad, acc[2]);  acc[2] = fma2(mA.y, w2ad, acc[2]);
                acc[3] = fma2(hA.y, w1bd, acc[3]);  acc[3] = fma2(mA.y, w2bd, acc[3]);
            }
        }
        {
            float* Ho = g_H + (size_t)t*B_*RH_ + (size_t)r*H_;
#pragma unroll
            for (int p=0;p<2;p++){
#pragma unroll
                for (int e=0;e<2;e++){
                    float lo, hi; up2(acc[p*2+e], lo, hi);
                    int g = gg + e*64;
                    __stcg(Ho + (size_t)(b0+2*p)*RH_   + g, tanhf(lo));
                    __stcg(Ho + (size_t)(b0+2*p+1)*RH_ + g, tanhf(hi));
                }
            }
        }
        if (t < T_-1) gbar(++bars * (unsigned)R_);
    }
}

// ============================================================================
// Dummy launch (profiling alignment: makes global launch idx 5 = rnn_persist)
// ============================================================================
__global__ void sync_reset_kernel(){ if (threadIdx.x == 0) g_arrive = 0u; }

// ============================================================================
// Kernel 3: out[t,b,o] = H[t][b][:] @ W_out + b_out   grid (T,2), 128 thr
// ============================================================================
__global__ __launch_bounds__(128) void out_kernel(const float* __restrict__ W_out,
                                                  const float* __restrict__ b_out,
                                                  float* __restrict__ out){
    int t = blockIdx.x, bh = blockIdx.y;             // bh: rows [bh*16, bh*16+16)
    __shared__ u64 hsh[128][9];                      // [kk][row-pair], padded
    int tid = threadIdx.x;
    int og = tid & 15, rp = tid >> 4;                // og*4 = o0 ; rp: row-pair 0..7
    int o0 = og*4;
    u64 acc[4];                                      // [row 0/1][o-pair 0/1]
    {
        const u64* bo = reinterpret_cast<const u64*>(b_out + o0);
        acc[0]=bo[0]; acc[1]=bo[1]; acc[2]=bo[0]; acc[3]=bo[1];
    }
    const float* Hb = g_H + (size_t)t*B_*RH_ + (size_t)(bh*16)*RH_;
    for (int kt=0; kt<RH_/128; kt++){
        __syncthreads();
        for (int idx = tid; idx < 16*128; idx += 128){
            int b = idx >> 7, kk = idx & 127;
            reinterpret_cast<float*>(&hsh[kk][b>>1])[b&1] = Hb[(size_t)b*RH_ + kt*128 + kk];
        }
        __syncthreads();
#pragma unroll 4
        for (int kk=0; kk<128; kk++){
            int k = kt*128 + kk;
            ulonglong2 w = *reinterpret_cast<const ulonglong2*>(W_out + (size_t)k*O_ + o0);
            u64 hp = hsh[kk][rp];
            float h0, h1; up2(hp, h0, h1);
            u64 h0d = pk2(h0,h0), h1d = pk2(h1,h1);
            acc[0] = fma2(w.x, h0d, acc[0]);  acc[1] = fma2(w.y, h0d, acc[1]);
            acc[2] = fma2(w.x, h1d, acc[2]);  acc[3] = fma2(w.y, h1d, acc[3]);
        }
    }
    u64* op = reinterpret_cast<u64*>(out);
    int row0 = bh*16 + rp*2;
    size_t base0 = ((size_t)(t*B_ + row0  )*O_ + o0) >> 1;
    size_t base1 = ((size_t)(t*B_ + row0+1)*O_ + o0) >> 1;
    op[base0] = acc[0];  op[base0+1] = acc[1];
    op[base1] = acc[2];  op[base1+1] = acc[3];
}

// ============================================================================
// Launch
// ============================================================================
extern "C" void kernel_launch(void* const* d_in, const int* in_sizes, int n_in,
                              void* d_out, int out_size){
    const float* x     = (const float*)d_in[0];
    const float* C     = (const float*)d_in[1];
    const float* W_ih  = (const float*)d_in[2];
    const float* W_hh  = (const float*)d_in[3];
    const float* W_rhh = (const float*)d_in[4];
    const float* bias  = (const float*)d_in[5];
    const float* W_out = (const float*)d_in[6];
    const float* b_out = (const float*)d_in[7];
    float* out = (float*)d_out;

    cudaFuncSetAttribute(rnn_persist, cudaFuncAttributeMaxDynamicSharedMemorySize,
                         SM_FLOATS * (int)sizeof(float));

    inp_kernel<<<dim3(R_, T_), 256>>>(x, W_ih, bias);     // resets g_arrive
    rnn_persist<<<R_, 512, SM_FLOATS * sizeof(float)>>>(W_hh, W_rhh, C);
    sync_reset_kernel<<<1, 32>>>();                       // profiling alignment
    out_kernel<<<dim3(T_, 2), 128>>>(W_out, b_out, out);
}